// round 8
// baseline (speedup 1.0000x reference)
#include <cuda_runtime.h>
#include <mma.h>
#include <cstdint>

using namespace nvcuda;

// Problem constants (fixed by the dataset)
#define NNODE 50000
#define NEDGE 800000
#define FIN   128
#define FH    256
#define FOUT  10
#define NG    512

// ---------------- scratch (device globals; no allocation) ----------------
__device__ float4 g_agg1[NNODE * (FIN / 4)];
__device__ float4 g_t1  [NNODE * (FH  / 4)];
__device__ float4 g_h   [NNODE * (FH  / 4)];
__device__ float4 g_agg2[NNODE * (FH  / 4)];
__device__ float4 g_t2  [NNODE * (FH  / 4)];
__device__ float4 g_psum[NG * (FH / 4)];
__device__ float  g_cnt [NG];
// CSR for incoming edges
__device__ int    g_deg [NNODE];
__device__ int    g_off [NNODE + 1];
__device__ int    g_cur [NNODE];
__device__ int    g_eidx[NEDGE];
// tf32-preconverted weights
__device__ float  g_W1a_t[FIN * FH];
__device__ float  g_W1b_t[FH * FH];
__device__ float  g_W2a_t[FH * FH];
__device__ float  g_W2b_t[FH * FH];

// ---------------- cp.async helpers ----------------
__device__ __forceinline__ void cp_async16(float* dst, const float* src) {
    uint32_t s = (uint32_t)__cvta_generic_to_shared(dst);
    asm volatile("cp.async.cg.shared.global [%0], [%1], 16;\n" :: "r"(s), "l"(src));
}
__device__ __forceinline__ void cp_async16z(float* dst, const float* src, int szbytes) {
    uint32_t s = (uint32_t)__cvta_generic_to_shared(dst);
    asm volatile("cp.async.cg.shared.global [%0], [%1], 16, %2;\n"
                 :: "r"(s), "l"(src), "r"(szbytes));
}
__device__ __forceinline__ void cp_commit() { asm volatile("cp.async.commit_group;\n"); }
template <int N>
__device__ __forceinline__ void cp_wait() { asm volatile("cp.async.wait_group %0;\n" :: "n"(N)); }

// ---------------- small utility kernels ----------------
__global__ void zero_k(float* __restrict__ p, int n) {
    int i = blockIdx.x * blockDim.x + threadIdx.x;
    if (i < n) p[i] = 0.0f;
}
__global__ void zeroi_k(int* __restrict__ p, int n) {
    int i = blockIdx.x * blockDim.x + threadIdx.x;
    if (i < n) p[i] = 0;
}
__global__ void wconv_k(const float* __restrict__ src, float* __restrict__ dst, int n) {
    int i = blockIdx.x * blockDim.x + threadIdx.x;
    if (i < n) dst[i] = wmma::__float_to_tf32(src[i]);
}

// ---------------- CSR build ----------------
__global__ void hist_k(const int* __restrict__ dst, int* __restrict__ deg) {
    int e = blockIdx.x * blockDim.x + threadIdx.x;
    if (e < NEDGE) atomicAdd(&deg[dst[e]], 1);
}

// exclusive prefix sum over NNODE entries, single block 1024 threads
__global__ void scan_k(const int* __restrict__ deg, int* __restrict__ off) {
    __shared__ int wsum[32];
    __shared__ int carry;
    int tid  = threadIdx.x;
    int lane = tid & 31;
    int w    = tid >> 5;
    if (tid == 0) carry = 0;
    __syncthreads();
    for (int base = 0; base < NNODE; base += 1024) {
        int i = base + tid;
        int v = (i < NNODE) ? deg[i] : 0;
        int s = v;
#pragma unroll
        for (int o = 1; o < 32; o <<= 1) {
            int t = __shfl_up_sync(0xffffffffu, s, o);
            if (lane >= o) s += t;
        }
        if (lane == 31) wsum[w] = s;
        __syncthreads();
        if (w == 0) {
            int ws = (lane < 32) ? wsum[lane] : 0;
#pragma unroll
            for (int o = 1; o < 32; o <<= 1) {
                int t = __shfl_up_sync(0xffffffffu, ws, o);
                if (lane >= o) ws += t;
            }
            wsum[lane] = ws;
        }
        __syncthreads();
        int wpre = (w == 0) ? 0 : wsum[w - 1];
        if (i < NNODE) off[i] = carry + wpre + s - v;
        __syncthreads();
        if (tid == 0) carry += wsum[31];
        __syncthreads();
    }
    if (threadIdx.x == 0) off[NNODE] = carry;
}

__global__ void copyoff_k(const int* __restrict__ off, int* __restrict__ cur) {
    int i = blockIdx.x * blockDim.x + threadIdx.x;
    if (i < NNODE) cur[i] = off[i];
}

__global__ void fill_k(const int* __restrict__ src, const int* __restrict__ dst,
                       int* __restrict__ cur, int* __restrict__ eidx) {
    int e = blockIdx.x * blockDim.x + threadIdx.x;
    if (e >= NEDGE) return;
    int p = atomicAdd(&cur[dst[e]], 1);
    eidx[p] = src[e];
}

// ---------------- CSR gather aggregation ----------------
// out[i] = tf32round( (1+eps)*feat[i] + sum_{j in in(i)} feat[j] )
template <int F4SHIFT>
__global__ void agg_k(const float4* __restrict__ feat, const float* __restrict__ eps,
                      const int* __restrict__ off, const int* __restrict__ eidx,
                      float4* __restrict__ out) {
    const int lanes = 1 << F4SHIFT;
    int node = blockIdx.x * (256 >> F4SHIFT) + (threadIdx.x >> F4SHIFT);
    int f    = threadIdx.x & (lanes - 1);
    if (node >= NNODE) return;
    float s = 1.0f + *eps;
    float4 x = feat[((size_t)node << F4SHIFT) + f];
    float4 a0 = make_float4(x.x * s, x.y * s, x.z * s, x.w * s);
    float4 a1 = make_float4(0.f, 0.f, 0.f, 0.f);
    float4 a2 = make_float4(0.f, 0.f, 0.f, 0.f);
    float4 a3 = make_float4(0.f, 0.f, 0.f, 0.f);
    int b = off[node], e = off[node + 1];
    int j = b;
    for (; j + 3 < e; j += 4) {
        int s0 = eidx[j], s1 = eidx[j + 1], s2 = eidx[j + 2], s3 = eidx[j + 3];
        float4 v0 = feat[((size_t)s0 << F4SHIFT) + f];
        float4 v1 = feat[((size_t)s1 << F4SHIFT) + f];
        float4 v2 = feat[((size_t)s2 << F4SHIFT) + f];
        float4 v3 = feat[((size_t)s3 << F4SHIFT) + f];
        a0.x += v0.x; a0.y += v0.y; a0.z += v0.z; a0.w += v0.w;
        a1.x += v1.x; a1.y += v1.y; a1.z += v1.z; a1.w += v1.w;
        a2.x += v2.x; a2.y += v2.y; a2.z += v2.z; a2.w += v2.w;
        a3.x += v3.x; a3.y += v3.y; a3.z += v3.z; a3.w += v3.w;
    }
    for (; j < e; j++) {
        float4 v = feat[((size_t)eidx[j] << F4SHIFT) + f];
        a0.x += v.x; a0.y += v.y; a0.z += v.z; a0.w += v.w;
    }
    a0.x += a1.x + a2.x + a3.x;
    a0.y += a1.y + a2.y + a3.y;
    a0.z += a1.z + a2.z + a3.z;
    a0.w += a1.w + a2.w + a3.w;
    // round to tf32 so the GEMM can skip fragment conversion
    a0.x = wmma::__float_to_tf32(a0.x);
    a0.y = wmma::__float_to_tf32(a0.y);
    a0.z = wmma::__float_to_tf32(a0.z);
    a0.w = wmma::__float_to_tf32(a0.w);
    out[((size_t)node << F4SHIFT) + f] = a0;
}

__global__ void count_k(const int* __restrict__ batch, float* __restrict__ cnt) {
    int i = blockIdx.x * blockDim.x + threadIdx.x;
    if (i < NNODE) atomicAdd(&cnt[batch[i]], 1.0f);
}

// ---------------- Pipelined TF32 tensor-core GEMM ----------------
// A is pre-rounded to tf32 by its producer -> no fragment conversion needed.
#define LDA 36
#define LDB 132
#define ASZ (128 * LDA)
#define BSZ (32 * LDB)
#define STGSZ (ASZ + BSZ)
#define NSTAGE 3
#define GEMM_SMEM (NSTAGE * STGSZ * 4)

__device__ __forceinline__ void gemm_load_slab(
    const float* __restrict__ A, const float* __restrict__ B,
    float* sm, int slot, int k0, int tid, int m0, int n0, int M, int K) {
    float* smA = sm + slot * STGSZ;
    float* smB = smA + ASZ;
#pragma unroll
    for (int t = 0; t < 4; t++) {
        int j   = tid + t * 256;
        int row = j >> 3;
        int c4  = (j & 7) * 4;
        bool ok = (m0 + row < M);
        const float* gs = &A[ok ? ((size_t)(m0 + row) * K + k0 + c4) : 0];
        cp_async16z(&smA[row * LDA + c4], gs, ok ? 16 : 0);
    }
#pragma unroll
    for (int t = 0; t < 4; t++) {
        int j   = tid + t * 256;
        int row = j >> 5;
        int c4  = (j & 31) * 4;
        cp_async16(&smB[row * LDB + c4], &B[(size_t)(k0 + row) * 256 + n0 + c4]);
    }
}

template <bool RELU, bool POOL, bool ROUND>
__global__ __launch_bounds__(256)
void gemm_tc(const float* __restrict__ A, const float* __restrict__ B,
             const float* __restrict__ bias, float* __restrict__ C,
             const int* __restrict__ batch, float* __restrict__ psum,
             int M, int K) {
    extern __shared__ float sm[];

    int tid  = threadIdx.x;
    int wid  = tid >> 5;
    int lane = tid & 31;
    int wm = wid >> 1;
    int wn = wid & 1;
    int m0 = blockIdx.y * 128;
    int n0 = blockIdx.x * 128;

    wmma::fragment<wmma::accumulator, 16, 16, 8, float> acc[2][4];
#pragma unroll
    for (int i = 0; i < 2; i++)
#pragma unroll
        for (int j = 0; j < 4; j++) wmma::fill_fragment(acc[i][j], 0.0f);

    int iters = K >> 5;

#pragma unroll
    for (int i = 0; i < NSTAGE - 1; i++) {
        if (i < iters)
            gemm_load_slab(A, B, sm, i, i * 32, tid, m0, n0, M, K);
        cp_commit();
    }

    for (int it = 0; it < iters; it++) {
        int pf = it + NSTAGE - 1;
        if (pf < iters)
            gemm_load_slab(A, B, sm, pf % NSTAGE, pf * 32, tid, m0, n0, M, K);
        cp_commit();
        cp_wait<NSTAGE - 1>();
        __syncthreads();

        float* smA = sm + (it % NSTAGE) * STGSZ;
        float* smB = smA + ASZ;
#pragma unroll
        for (int ks = 0; ks < 4; ks++) {
            wmma::fragment<wmma::matrix_a, 16, 16, 8, wmma::precision::tf32,
                           wmma::row_major> af[2];
            wmma::fragment<wmma::matrix_b, 16, 16, 8, wmma::precision::tf32,
                           wmma::row_major> bf[4];
#pragma unroll
            for (int i = 0; i < 2; i++)
                wmma::load_matrix_sync(af[i], &smA[(wm * 32 + i * 16) * LDA + ks * 8], LDA);
#pragma unroll
            for (int j = 0; j < 4; j++)
                wmma::load_matrix_sync(bf[j], &smB[(ks * 8) * LDB + wn * 64 + j * 16], LDB);
#pragma unroll
            for (int i = 0; i < 2; i++)
#pragma unroll
                for (int j = 0; j < 4; j++)
                    wmma::mma_sync(acc[i][j], af[i], bf[j], acc[i][j]);
        }
        __syncthreads();
    }

    // ---- epilogue ----
    const int LDS_ = 20;
    float* St = sm + wid * (16 * LDS_);
#pragma unroll
    for (int i = 0; i < 2; i++)
#pragma unroll
        for (int j = 0; j < 4; j++) {
            wmma::store_matrix_sync(St, acc[i][j], LDS_, wmma::mem_row_major);
            __syncwarp();
            int r   = lane >> 1;
            int c   = (lane & 1) * 8;
            int row = m0 + wm * 32 + i * 16 + r;
            int col = n0 + wn * 64 + j * 16 + c;
            if (row < M) {
                float v[8];
#pragma unroll
                for (int u = 0; u < 8; u++) {
                    v[u] = St[r * LDS_ + c + u] + bias[col + u];
                    if (RELU) v[u] = fmaxf(v[u], 0.0f);
                    if (ROUND) v[u] = wmma::__float_to_tf32(v[u]);
                }
                if (POOL) {
                    int g = batch[row];
                    float4* pp = (float4*)&psum[(size_t)g * 256 + col];
                    atomicAdd(&pp[0], make_float4(v[0], v[1], v[2], v[3]));
                    atomicAdd(&pp[1], make_float4(v[4], v[5], v[6], v[7]));
                } else {
                    float4* cp = (float4*)&C[(size_t)row * 256 + col];
                    cp[0] = make_float4(v[0], v[1], v[2], v[3]);
                    cp[1] = make_float4(v[4], v[5], v[6], v[7]);
                }
            }
            __syncwarp();
        }
}

// ---------------- final: mean, linear [256->10], log_softmax ----------------
__global__ void final_k(const float* __restrict__ psum, const float* __restrict__ cnt,
                        const float* __restrict__ Wlin, const float* __restrict__ blin,
                        float* __restrict__ out) {
    int g = blockIdx.x;
    int lane = threadIdx.x;
    float inv = 1.0f / fmaxf(cnt[g], 1.0f);
    float acc[FOUT];
#pragma unroll
    for (int o = 0; o < FOUT; o++) acc[o] = 0.0f;
    for (int h = lane; h < FH; h += 32) {
        float p = psum[g * FH + h] * inv;
#pragma unroll
        for (int o = 0; o < FOUT; o++) acc[o] += p * Wlin[h * FOUT + o];
    }
#pragma unroll
    for (int off = 16; off > 0; off >>= 1)
#pragma unroll
        for (int o = 0; o < FOUT; o++)
            acc[o] += __shfl_down_sync(0xffffffffu, acc[o], off);
    if (lane == 0) {
        float z[FOUT];
        float m = -1e30f;
#pragma unroll
        for (int o = 0; o < FOUT; o++) { z[o] = acc[o] + blin[o]; m = fmaxf(m, z[o]); }
        float s = 0.0f;
#pragma unroll
        for (int o = 0; o < FOUT; o++) s += __expf(z[o] - m);
        float l = logf(s);
#pragma unroll
        for (int o = 0; o < FOUT; o++) out[g * FOUT + o] = z[o] - m - l;
    }
}

// ---------------- launcher ----------------
extern "C" void kernel_launch(void* const* d_in, const int* in_sizes, int n_in,
                              void* d_out, int out_size) {
    const float* x     = (const float*)d_in[0];
    const int*   ei    = (const int*)  d_in[1];
    const int*   batch = (const int*)  d_in[2];
    const float* eps1  = (const float*)d_in[3];
    const float* W1a   = (const float*)d_in[4];
    const float* b1a   = (const float*)d_in[5];
    const float* W1b   = (const float*)d_in[6];
    const float* b1b   = (const float*)d_in[7];
    const float* eps2  = (const float*)d_in[8];
    const float* W2a   = (const float*)d_in[9];
    const float* b2a   = (const float*)d_in[10];
    const float* W2b   = (const float*)d_in[11];
    const float* b2b   = (const float*)d_in[12];
    const float* Wlin  = (const float*)d_in[13];
    const float* blin  = (const float*)d_in[14];
    float* out = (float*)d_out;

    void *p_agg1, *p_t1, *p_h, *p_agg2, *p_t2, *p_psum, *p_cnt;
    void *p_deg, *p_off, *p_cur, *p_eidx;
    void *p_w1a, *p_w1b, *p_w2a, *p_w2b;
    cudaGetSymbolAddress(&p_agg1, g_agg1);
    cudaGetSymbolAddress(&p_t1,   g_t1);
    cudaGetSymbolAddress(&p_h,    g_h);
    cudaGetSymbolAddress(&p_agg2, g_agg2);
    cudaGetSymbolAddress(&p_t2,   g_t2);
    cudaGetSymbolAddress(&p_psum, g_psum);
    cudaGetSymbolAddress(&p_cnt,  g_cnt);
    cudaGetSymbolAddress(&p_deg,  g_deg);
    cudaGetSymbolAddress(&p_off,  g_off);
    cudaGetSymbolAddress(&p_cur,  g_cur);
    cudaGetSymbolAddress(&p_eidx, g_eidx);
    cudaGetSymbolAddress(&p_w1a, g_W1a_t);
    cudaGetSymbolAddress(&p_w1b, g_W1b_t);
    cudaGetSymbolAddress(&p_w2a, g_W2a_t);
    cudaGetSymbolAddress(&p_w2b, g_W2b_t);
    float4* agg1 = (float4*)p_agg1;
    float4* t1   = (float4*)p_t1;
    float4* h    = (float4*)p_h;
    float4* agg2 = (float4*)p_agg2;
    float4* t2   = (float4*)p_t2;
    float*  psum = (float*)p_psum;
    float*  cnt  = (float*)p_cnt;
    int* deg  = (int*)p_deg;
    int* off  = (int*)p_off;
    int* cur  = (int*)p_cur;
    int* eidx = (int*)p_eidx;
    float*  W1a_t = (float*)p_w1a;
    float*  W1b_t = (float*)p_w1b;
    float*  W2a_t = (float*)p_w2a;
    float*  W2b_t = (float*)p_w2b;

    cudaFuncSetAttribute(gemm_tc<true,  false, true>,
                         cudaFuncAttributeMaxDynamicSharedMemorySize, GEMM_SMEM);
    cudaFuncSetAttribute(gemm_tc<true,  false, false>,
                         cudaFuncAttributeMaxDynamicSharedMemorySize, GEMM_SMEM);
    cudaFuncSetAttribute(gemm_tc<false, true,  false>,
                         cudaFuncAttributeMaxDynamicSharedMemorySize, GEMM_SMEM);

    const int* src = ei;
    const int* dst = ei + NEDGE;
    const int T = 256;

    // ---- CSR build (incoming edges per node) ----
    zeroi_k<<<(NNODE + T - 1) / T, T>>>(deg, NNODE);
    hist_k<<<(NEDGE + T - 1) / T, T>>>(dst, deg);
    scan_k<<<1, 1024>>>(deg, off);
    copyoff_k<<<(NNODE + T - 1) / T, T>>>(off, cur);
    fill_k<<<(NEDGE + T - 1) / T, T>>>(src, dst, cur, eidx);

    // ---- weights to tf32 ----
    wconv_k<<<(FIN * FH + T - 1) / T, T>>>(W1a, W1a_t, FIN * FH);
    wconv_k<<<(FH * FH + T - 1) / T, T>>>(W1b, W1b_t, FH * FH);
    wconv_k<<<(FH * FH + T - 1) / T, T>>>(W2a, W2a_t, FH * FH);
    wconv_k<<<(FH * FH + T - 1) / T, T>>>(W2b, W2b_t, FH * FH);

    // ---- layer 1 ----
    agg_k<5><<<(NNODE * 32 + T - 1) / T, T>>>((const float4*)x, eps1, off, eidx, agg1);

    dim3 gdim(2, (NNODE + 127) / 128);
    // t1 = relu(agg1 @ W1a + b1a), rounded to tf32 (consumed by GEMM2)
    gemm_tc<true, false, true><<<gdim, 256, GEMM_SMEM>>>(
        (const float*)agg1, W1a_t, b1a, (float*)t1, nullptr, nullptr, NNODE, FIN);
    // h = relu(t1 @ W1b + b1b)  (consumed by agg_k, which rounds its own output)
    gemm_tc<true, false, false><<<gdim, 256, GEMM_SMEM>>>(
        (const float*)t1, W1b_t, b1b, (float*)h, nullptr, nullptr, NNODE, FH);

    // ---- layer 2 ----
    agg_k<6><<<(NNODE * 64 + T - 1) / T, T>>>(h, eps2, off, eidx, agg2);
    // t2 = relu(agg2 @ W2a + b2a), rounded to tf32 (consumed by GEMM4)
    gemm_tc<true, false, true><<<gdim, 256, GEMM_SMEM>>>(
        (const float*)agg2, W2a_t, b2a, (float*)t2, nullptr, nullptr, NNODE, FH);

    // ---- pooling setup ----
    zero_k<<<(NG * FH + T - 1) / T, T>>>(psum, NG * FH);
    zero_k<<<(NG + T - 1) / T, T>>>(cnt, NG);
    count_k<<<(NNODE + T - 1) / T, T>>>(batch, cnt);

    // h2 = t2 @ W2b + b2b fused with global-mean-pool partial sums
    gemm_tc<false, true, false><<<gdim, 256, GEMM_SMEM>>>(
        (const float*)t2, W2b_t, b2b, nullptr, batch, psum, NNODE, FH);

    // mean + linear + log_softmax
    final_k<<<NG, 32>>>(psum, cnt, Wlin, blin, out);
}

// round 9
// speedup vs baseline: 1.1379x; 1.1379x over previous
#include <cuda_runtime.h>
#include <mma.h>
#include <cstdint>

using namespace nvcuda;

// Problem constants (fixed by the dataset)
#define NNODE 50000
#define NEDGE 800000
#define FIN   128
#define FH    256
#define FOUT  10
#define NG    512

// ---------------- scratch (device globals; no allocation) ----------------
__device__ float4 g_agg1[NNODE * (FIN / 4)];
__device__ float4 g_t1  [NNODE * (FH  / 4)];
__device__ float4 g_h   [NNODE * (FH  / 4)];
__device__ float4 g_agg2[NNODE * (FH  / 4)];
__device__ float4 g_t2  [NNODE * (FH  / 4)];
__device__ float4 g_psum[NG * (FH / 4)];
__device__ float  g_cnt [NG];
// CSR for incoming edges
__device__ int    g_deg [NNODE];
__device__ int    g_off [NNODE + 1];
__device__ int    g_cur [NNODE];
__device__ int    g_eidx[NEDGE];
// tf32-preconverted weights
__device__ float  g_W1a_t[FIN * FH];
__device__ float  g_W1b_t[FH * FH];
__device__ float  g_W2a_t[FH * FH];
__device__ float  g_W2b_t[FH * FH];

// ---------------- cp.async helpers ----------------
__device__ __forceinline__ void cp_async16(float* dst, const float* src) {
    uint32_t s = (uint32_t)__cvta_generic_to_shared(dst);
    asm volatile("cp.async.cg.shared.global [%0], [%1], 16;\n" :: "r"(s), "l"(src));
}
__device__ __forceinline__ void cp_async16z(float* dst, const float* src, int szbytes) {
    uint32_t s = (uint32_t)__cvta_generic_to_shared(dst);
    asm volatile("cp.async.cg.shared.global [%0], [%1], 16, %2;\n"
                 :: "r"(s), "l"(src), "r"(szbytes));
}
__device__ __forceinline__ void cp_commit() { asm volatile("cp.async.commit_group;\n"); }
template <int N>
__device__ __forceinline__ void cp_wait() { asm volatile("cp.async.wait_group %0;\n" :: "n"(N)); }

// ---------------- small utility kernels ----------------
// zero psum (NG*FH floats) and cnt (NG floats) in one launch
__global__ void zero_pool_k(float* __restrict__ psum, float* __restrict__ cnt) {
    int i = blockIdx.x * blockDim.x + threadIdx.x;
    if (i < NG * FH) psum[i] = 0.0f;
    else if (i < NG * FH + NG) cnt[i - NG * FH] = 0.0f;
}
__global__ void zeroi_k(int* __restrict__ p, int n) {
    int i = blockIdx.x * blockDim.x + threadIdx.x;
    if (i < n) p[i] = 0;
}
// convert all four weight matrices to tf32 in one launch
__global__ void wconv_all_k(const float* __restrict__ W1a, const float* __restrict__ W1b,
                            const float* __restrict__ W2a, const float* __restrict__ W2b,
                            float* __restrict__ D1a, float* __restrict__ D1b,
                            float* __restrict__ D2a, float* __restrict__ D2b) {
    int i = blockIdx.x * blockDim.x + threadIdx.x;
    const int S1 = FIN * FH;              // 32768
    const int S2 = S1 + FH * FH;          // 98304
    const int S3 = S2 + FH * FH;          // 163840
    const int S4 = S3 + FH * FH;          // 229376
    if (i < S1)       D1a[i]      = wmma::__float_to_tf32(W1a[i]);
    else if (i < S2)  D1b[i - S1] = wmma::__float_to_tf32(W1b[i - S1]);
    else if (i < S3)  D2a[i - S2] = wmma::__float_to_tf32(W2a[i - S2]);
    else if (i < S4)  D2b[i - S3] = wmma::__float_to_tf32(W2b[i - S3]);
}

// ---------------- CSR build ----------------
__global__ void hist_k(const int* __restrict__ dst, int* __restrict__ deg) {
    int e = blockIdx.x * blockDim.x + threadIdx.x;
    if (e < NEDGE) atomicAdd(&deg[dst[e]], 1);
}

// exclusive prefix sum over NNODE entries; writes off AND cur
__global__ void scan_k(const int* __restrict__ deg, int* __restrict__ off,
                       int* __restrict__ cur) {
    __shared__ int wsum[32];
    __shared__ int carry;
    int tid  = threadIdx.x;
    int lane = tid & 31;
    int w    = tid >> 5;
    if (tid == 0) carry = 0;
    __syncthreads();
    for (int base = 0; base < NNODE; base += 1024) {
        int i = base + tid;
        int v = (i < NNODE) ? deg[i] : 0;
        int s = v;
#pragma unroll
        for (int o = 1; o < 32; o <<= 1) {
            int t = __shfl_up_sync(0xffffffffu, s, o);
            if (lane >= o) s += t;
        }
        if (lane == 31) wsum[w] = s;
        __syncthreads();
        if (w == 0) {
            int ws = (lane < 32) ? wsum[lane] : 0;
#pragma unroll
            for (int o = 1; o < 32; o <<= 1) {
                int t = __shfl_up_sync(0xffffffffu, ws, o);
                if (lane >= o) ws += t;
            }
            wsum[lane] = ws;
        }
        __syncthreads();
        int wpre = (w == 0) ? 0 : wsum[w - 1];
        if (i < NNODE) {
            int e = carry + wpre + s - v;   // exclusive
            off[i] = e;
            cur[i] = e;
        }
        __syncthreads();
        if (tid == 0) carry += wsum[31];
        __syncthreads();
    }
    if (threadIdx.x == 0) off[NNODE] = carry;
}

__global__ void fill_k(const int* __restrict__ src, const int* __restrict__ dst,
                       int* __restrict__ cur, int* __restrict__ eidx) {
    int e = blockIdx.x * blockDim.x + threadIdx.x;
    if (e >= NEDGE) return;
    int p = atomicAdd(&cur[dst[e]], 1);
    eidx[p] = src[e];
}

// ---------------- CSR gather aggregation ----------------
// out[i] = (1+eps)*feat[i] + sum_{j in in(i)} feat[j]   (exact R6 version)
template <int F4SHIFT>
__global__ void agg_k(const float4* __restrict__ feat, const float* __restrict__ eps,
                      const int* __restrict__ off, const int* __restrict__ eidx,
                      float4* __restrict__ out) {
    const int lanes = 1 << F4SHIFT;
    int node = blockIdx.x * (256 >> F4SHIFT) + (threadIdx.x >> F4SHIFT);
    int f    = threadIdx.x & (lanes - 1);
    if (node >= NNODE) return;
    float s = 1.0f + *eps;
    float4 x = feat[((size_t)node << F4SHIFT) + f];
    float4 a0 = make_float4(x.x * s, x.y * s, x.z * s, x.w * s);
    float4 a1 = make_float4(0.f, 0.f, 0.f, 0.f);
    float4 a2 = make_float4(0.f, 0.f, 0.f, 0.f);
    float4 a3 = make_float4(0.f, 0.f, 0.f, 0.f);
    int b = off[node], e = off[node + 1];
    int j = b;
    for (; j + 3 < e; j += 4) {
        int s0 = eidx[j], s1 = eidx[j + 1], s2 = eidx[j + 2], s3 = eidx[j + 3];
        float4 v0 = feat[((size_t)s0 << F4SHIFT) + f];
        float4 v1 = feat[((size_t)s1 << F4SHIFT) + f];
        float4 v2 = feat[((size_t)s2 << F4SHIFT) + f];
        float4 v3 = feat[((size_t)s3 << F4SHIFT) + f];
        a0.x += v0.x; a0.y += v0.y; a0.z += v0.z; a0.w += v0.w;
        a1.x += v1.x; a1.y += v1.y; a1.z += v1.z; a1.w += v1.w;
        a2.x += v2.x; a2.y += v2.y; a2.z += v2.z; a2.w += v2.w;
        a3.x += v3.x; a3.y += v3.y; a3.z += v3.z; a3.w += v3.w;
    }
    for (; j < e; j++) {
        float4 v = feat[((size_t)eidx[j] << F4SHIFT) + f];
        a0.x += v.x; a0.y += v.y; a0.z += v.z; a0.w += v.w;
    }
    a0.x += a1.x + a2.x + a3.x;
    a0.y += a1.y + a2.y + a3.y;
    a0.z += a1.z + a2.z + a3.z;
    a0.w += a1.w + a2.w + a3.w;
    out[((size_t)node << F4SHIFT) + f] = a0;
}

__global__ void count_k(const int* __restrict__ batch, float* __restrict__ cnt) {
    int i = blockIdx.x * blockDim.x + threadIdx.x;
    if (i < NNODE) atomicAdd(&cnt[batch[i]], 1.0f);
}

// ---------------- Pipelined TF32 tensor-core GEMM (EXACT R6 inner loop) ----------------
#define LDA 36
#define LDB 132
#define ASZ (128 * LDA)
#define BSZ (32 * LDB)
#define STGSZ (ASZ + BSZ)
#define NSTAGE 3
#define GEMM_SMEM (NSTAGE * STGSZ * 4)

__device__ __forceinline__ void gemm_load_slab(
    const float* __restrict__ A, const float* __restrict__ B,
    float* sm, int slot, int k0, int tid, int m0, int n0, int M, int K) {
    float* smA = sm + slot * STGSZ;
    float* smB = smA + ASZ;
#pragma unroll
    for (int t = 0; t < 4; t++) {
        int j   = tid + t * 256;
        int row = j >> 3;
        int c4  = (j & 7) * 4;
        bool ok = (m0 + row < M);
        const float* gs = &A[ok ? ((size_t)(m0 + row) * K + k0 + c4) : 0];
        cp_async16z(&smA[row * LDA + c4], gs, ok ? 16 : 0);
    }
#pragma unroll
    for (int t = 0; t < 4; t++) {
        int j   = tid + t * 256;
        int row = j >> 5;
        int c4  = (j & 31) * 4;
        cp_async16(&smB[row * LDB + c4], &B[(size_t)(k0 + row) * 256 + n0 + c4]);
    }
}

template <bool RELU, bool POOL>
__global__ __launch_bounds__(256)
void gemm_tc(const float* __restrict__ A, const float* __restrict__ B,
             const float* __restrict__ bias, float* __restrict__ C,
             const int* __restrict__ batch, float* __restrict__ psum,
             int M, int K) {
    extern __shared__ float sm[];

    int tid  = threadIdx.x;
    int wid  = tid >> 5;
    int lane = tid & 31;
    int wm = wid >> 1;
    int wn = wid & 1;
    int m0 = blockIdx.y * 128;
    int n0 = blockIdx.x * 128;

    wmma::fragment<wmma::accumulator, 16, 16, 8, float> acc[2][4];
#pragma unroll
    for (int i = 0; i < 2; i++)
#pragma unroll
        for (int j = 0; j < 4; j++) wmma::fill_fragment(acc[i][j], 0.0f);

    int iters = K >> 5;

#pragma unroll
    for (int i = 0; i < NSTAGE - 1; i++) {
        if (i < iters)
            gemm_load_slab(A, B, sm, i, i * 32, tid, m0, n0, M, K);
        cp_commit();
    }

    for (int it = 0; it < iters; it++) {
        int pf = it + NSTAGE - 1;
        if (pf < iters)
            gemm_load_slab(A, B, sm, pf % NSTAGE, pf * 32, tid, m0, n0, M, K);
        cp_commit();
        cp_wait<NSTAGE - 1>();
        __syncthreads();

        float* smA = sm + (it % NSTAGE) * STGSZ;
        float* smB = smA + ASZ;
#pragma unroll
        for (int ks = 0; ks < 4; ks++) {
            wmma::fragment<wmma::matrix_a, 16, 16, 8, wmma::precision::tf32,
                           wmma::row_major> af[2];
            wmma::fragment<wmma::matrix_b, 16, 16, 8, wmma::precision::tf32,
                           wmma::row_major> bf[4];
#pragma unroll
            for (int i = 0; i < 2; i++) {
                wmma::load_matrix_sync(af[i], &smA[(wm * 32 + i * 16) * LDA + ks * 8], LDA);
#pragma unroll
                for (int t = 0; t < af[i].num_elements; t++)
                    af[i].x[t] = wmma::__float_to_tf32(af[i].x[t]);
            }
#pragma unroll
            for (int j = 0; j < 4; j++)
                wmma::load_matrix_sync(bf[j], &smB[(ks * 8) * LDB + wn * 64 + j * 16], LDB);
#pragma unroll
            for (int i = 0; i < 2; i++)
#pragma unroll
                for (int j = 0; j < 4; j++)
                    wmma::mma_sync(acc[i][j], af[i], bf[j], acc[i][j]);
        }
        __syncthreads();
    }

    // ---- epilogue ----
    const int LDS_ = 20;
    float* St = sm + wid * (16 * LDS_);
#pragma unroll
    for (int i = 0; i < 2; i++)
#pragma unroll
        for (int j = 0; j < 4; j++) {
            wmma::store_matrix_sync(St, acc[i][j], LDS_, wmma::mem_row_major);
            __syncwarp();
            int r   = lane >> 1;
            int c   = (lane & 1) * 8;
            int row = m0 + wm * 32 + i * 16 + r;
            int col = n0 + wn * 64 + j * 16 + c;
            if (row < M) {
                float v[8];
#pragma unroll
                for (int u = 0; u < 8; u++) {
                    v[u] = St[r * LDS_ + c + u] + bias[col + u];
                    if (RELU) v[u] = fmaxf(v[u], 0.0f);
                }
                if (POOL) {
                    int g = batch[row];
                    float4* pp = (float4*)&psum[(size_t)g * 256 + col];
                    atomicAdd(&pp[0], make_float4(v[0], v[1], v[2], v[3]));
                    atomicAdd(&pp[1], make_float4(v[4], v[5], v[6], v[7]));
                } else {
                    float4* cp = (float4*)&C[(size_t)row * 256 + col];
                    cp[0] = make_float4(v[0], v[1], v[2], v[3]);
                    cp[1] = make_float4(v[4], v[5], v[6], v[7]);
                }
            }
            __syncwarp();
        }
}

// ---------------- final: mean, linear [256->10], log_softmax ----------------
__global__ void final_k(const float* __restrict__ psum, const float* __restrict__ cnt,
                        const float* __restrict__ Wlin, const float* __restrict__ blin,
                        float* __restrict__ out) {
    int g = blockIdx.x;
    int lane = threadIdx.x;
    float inv = 1.0f / fmaxf(cnt[g], 1.0f);
    float acc[FOUT];
#pragma unroll
    for (int o = 0; o < FOUT; o++) acc[o] = 0.0f;
    for (int h = lane; h < FH; h += 32) {
        float p = psum[g * FH + h] * inv;
#pragma unroll
        for (int o = 0; o < FOUT; o++) acc[o] += p * Wlin[h * FOUT + o];
    }
#pragma unroll
    for (int off = 16; off > 0; off >>= 1)
#pragma unroll
        for (int o = 0; o < FOUT; o++)
            acc[o] += __shfl_down_sync(0xffffffffu, acc[o], off);
    if (lane == 0) {
        float z[FOUT];
        float m = -1e30f;
#pragma unroll
        for (int o = 0; o < FOUT; o++) { z[o] = acc[o] + blin[o]; m = fmaxf(m, z[o]); }
        float s = 0.0f;
#pragma unroll
        for (int o = 0; o < FOUT; o++) s += __expf(z[o] - m);
        float l = logf(s);
#pragma unroll
        for (int o = 0; o < FOUT; o++) out[g * FOUT + o] = z[o] - m - l;
    }
}

// ---------------- launcher ----------------
extern "C" void kernel_launch(void* const* d_in, const int* in_sizes, int n_in,
                              void* d_out, int out_size) {
    const float* x     = (const float*)d_in[0];
    const int*   ei    = (const int*)  d_in[1];
    const int*   batch = (const int*)  d_in[2];
    const float* eps1  = (const float*)d_in[3];
    const float* W1a   = (const float*)d_in[4];
    const float* b1a   = (const float*)d_in[5];
    const float* W1b   = (const float*)d_in[6];
    const float* b1b   = (const float*)d_in[7];
    const float* eps2  = (const float*)d_in[8];
    const float* W2a   = (const float*)d_in[9];
    const float* b2a   = (const float*)d_in[10];
    const float* W2b   = (const float*)d_in[11];
    const float* b2b   = (const float*)d_in[12];
    const float* Wlin  = (const float*)d_in[13];
    const float* blin  = (const float*)d_in[14];
    float* out = (float*)d_out;

    void *p_agg1, *p_t1, *p_h, *p_agg2, *p_t2, *p_psum, *p_cnt;
    void *p_deg, *p_off, *p_cur, *p_eidx;
    void *p_w1a, *p_w1b, *p_w2a, *p_w2b;
    cudaGetSymbolAddress(&p_agg1, g_agg1);
    cudaGetSymbolAddress(&p_t1,   g_t1);
    cudaGetSymbolAddress(&p_h,    g_h);
    cudaGetSymbolAddress(&p_agg2, g_agg2);
    cudaGetSymbolAddress(&p_t2,   g_t2);
    cudaGetSymbolAddress(&p_psum, g_psum);
    cudaGetSymbolAddress(&p_cnt,  g_cnt);
    cudaGetSymbolAddress(&p_deg,  g_deg);
    cudaGetSymbolAddress(&p_off,  g_off);
    cudaGetSymbolAddress(&p_cur,  g_cur);
    cudaGetSymbolAddress(&p_eidx, g_eidx);
    cudaGetSymbolAddress(&p_w1a, g_W1a_t);
    cudaGetSymbolAddress(&p_w1b, g_W1b_t);
    cudaGetSymbolAddress(&p_w2a, g_W2a_t);
    cudaGetSymbolAddress(&p_w2b, g_W2b_t);
    float4* agg1 = (float4*)p_agg1;
    float4* t1   = (float4*)p_t1;
    float4* h    = (float4*)p_h;
    float4* agg2 = (float4*)p_agg2;
    float4* t2   = (float4*)p_t2;
    float*  psum = (float*)p_psum;
    float*  cnt  = (float*)p_cnt;
    int* deg  = (int*)p_deg;
    int* off  = (int*)p_off;
    int* cur  = (int*)p_cur;
    int* eidx = (int*)p_eidx;
    float*  W1a_t = (float*)p_w1a;
    float*  W1b_t = (float*)p_w1b;
    float*  W2a_t = (float*)p_w2a;
    float*  W2b_t = (float*)p_w2b;

    cudaFuncSetAttribute(gemm_tc<true,  false>,
                         cudaFuncAttributeMaxDynamicSharedMemorySize, GEMM_SMEM);
    cudaFuncSetAttribute(gemm_tc<false, true>,
                         cudaFuncAttributeMaxDynamicSharedMemorySize, GEMM_SMEM);

    const int* src = ei;
    const int* dst = ei + NEDGE;
    const int T = 256;

    // ---- CSR build (incoming edges per node) ----
    zeroi_k<<<(NNODE + T - 1) / T, T>>>(deg, NNODE);
    hist_k<<<(NEDGE + T - 1) / T, T>>>(dst, deg);
    scan_k<<<1, 1024>>>(deg, off, cur);
    fill_k<<<(NEDGE + T - 1) / T, T>>>(src, dst, cur, eidx);

    // ---- weights to tf32 (single launch) ----
    {
        int total = FIN * FH + 3 * FH * FH;
        wconv_all_k<<<(total + T - 1) / T, T>>>(W1a, W1b, W2a, W2b,
                                                W1a_t, W1b_t, W2a_t, W2b_t);
    }

    // ---- layer 1 ----
    agg_k<5><<<(NNODE * 32 + T - 1) / T, T>>>((const float4*)x, eps1, off, eidx, agg1);

    dim3 gdim(2, (NNODE + 127) / 128);
    gemm_tc<true, false><<<gdim, 256, GEMM_SMEM>>>(
        (const float*)agg1, W1a_t, b1a, (float*)t1, nullptr, nullptr, NNODE, FIN);
    gemm_tc<true, false><<<gdim, 256, GEMM_SMEM>>>(
        (const float*)t1, W1b_t, b1b, (float*)h, nullptr, nullptr, NNODE, FH);

    // ---- layer 2 ----
    agg_k<6><<<(NNODE * 64 + T - 1) / T, T>>>(h, eps2, off, eidx, agg2);
    gemm_tc<true, false><<<gdim, 256, GEMM_SMEM>>>(
        (const float*)agg2, W2a_t, b2a, (float*)t2, nullptr, nullptr, NNODE, FH);

    // ---- pooling setup (single zero launch) ----
    zero_pool_k<<<(NG * FH + NG + T - 1) / T, T>>>(psum, cnt);
    count_k<<<(NNODE + T - 1) / T, T>>>(batch, cnt);

    // h2 = t2 @ W2b + b2b fused with global-mean-pool partial sums
    gemm_tc<false, true><<<gdim, 256, GEMM_SMEM>>>(
        (const float*)t2, W2b_t, b2b, nullptr, batch, psum, NNODE, FH);

    // mean + linear + log_softmax
    final_k<<<NG, 32>>>(psum, cnt, Wlin, blin, out);
}

// round 10
// speedup vs baseline: 1.1625x; 1.0216x over previous
#include <cuda_runtime.h>
#include <mma.h>
#include <cstdint>

using namespace nvcuda;

// Problem constants (fixed by the dataset)
#define NNODE 50000
#define NEDGE 800000
#define FIN   128
#define FH    256
#define FOUT  10
#define NG    512

// ---------------- scratch (device globals; no allocation) ----------------
__device__ float4 g_agg1[NNODE * (FIN / 4)];
__device__ float4 g_t1  [NNODE * (FH  / 4)];
__device__ float4 g_h   [NNODE * (FH  / 4)];
__device__ float4 g_agg2[NNODE * (FH  / 4)];
__device__ float4 g_t2  [NNODE * (FH  / 4)];
__device__ float4 g_psum[NG * (FH / 4)];
__device__ float  g_cnt [NG];
// CSR for incoming edges
__device__ int    g_deg [NNODE];
__device__ int    g_off [NNODE + 1];
__device__ int    g_cur [NNODE];
__device__ int    g_eidx[NEDGE];
// tf32-preconverted weights
__device__ float  g_W1a_t[FIN * FH];
__device__ float  g_W1b_t[FH * FH];
__device__ float  g_W2a_t[FH * FH];
__device__ float  g_W2b_t[FH * FH];

// ---------------- cp.async helpers ----------------
__device__ __forceinline__ void cp_async16(float* dst, const float* src) {
    uint32_t s = (uint32_t)__cvta_generic_to_shared(dst);
    asm volatile("cp.async.cg.shared.global [%0], [%1], 16;\n" :: "r"(s), "l"(src));
}
__device__ __forceinline__ void cp_async16z(float* dst, const float* src, int szbytes) {
    uint32_t s = (uint32_t)__cvta_generic_to_shared(dst);
    asm volatile("cp.async.cg.shared.global [%0], [%1], 16, %2;\n"
                 :: "r"(s), "l"(src), "r"(szbytes));
}
__device__ __forceinline__ void cp_commit() { asm volatile("cp.async.commit_group;\n"); }
template <int N>
__device__ __forceinline__ void cp_wait() { asm volatile("cp.async.wait_group %0;\n" :: "n"(N)); }

// ---------------- small utility kernels ----------------
// zero psum (NG*FH floats) and cnt (NG floats) in one launch
__global__ void zero_pool_k(float* __restrict__ psum, float* __restrict__ cnt) {
    int i = blockIdx.x * blockDim.x + threadIdx.x;
    if (i < NG * FH) psum[i] = 0.0f;
    else if (i < NG * FH + NG) cnt[i - NG * FH] = 0.0f;
}
__global__ void zeroi_k(int* __restrict__ p, int n) {
    int i = blockIdx.x * blockDim.x + threadIdx.x;
    if (i < n) p[i] = 0;
}
// convert all four weight matrices to tf32 in one launch
__global__ void wconv_all_k(const float* __restrict__ W1a, const float* __restrict__ W1b,
                            const float* __restrict__ W2a, const float* __restrict__ W2b,
                            float* __restrict__ D1a, float* __restrict__ D1b,
                            float* __restrict__ D2a, float* __restrict__ D2b) {
    int i = blockIdx.x * blockDim.x + threadIdx.x;
    const int S1 = FIN * FH;              // 32768
    const int S2 = S1 + FH * FH;          // 98304
    const int S3 = S2 + FH * FH;          // 163840
    const int S4 = S3 + FH * FH;          // 229376
    if (i < S1)       D1a[i]      = wmma::__float_to_tf32(W1a[i]);
    else if (i < S2)  D1b[i - S1] = wmma::__float_to_tf32(W1b[i - S1]);
    else if (i < S3)  D2a[i - S2] = wmma::__float_to_tf32(W2a[i - S2]);
    else if (i < S4)  D2b[i - S3] = wmma::__float_to_tf32(W2b[i - S3]);
}

// ---------------- CSR build ----------------
__global__ void hist_k(const int* __restrict__ dst, int* __restrict__ deg) {
    int e = blockIdx.x * blockDim.x + threadIdx.x;
    if (e < NEDGE) atomicAdd(&deg[dst[e]], 1);
}

// exclusive prefix sum over NNODE entries; writes off AND cur
__global__ void scan_k(const int* __restrict__ deg, int* __restrict__ off,
                       int* __restrict__ cur) {
    __shared__ int wsum[32];
    __shared__ int carry;
    int tid  = threadIdx.x;
    int lane = tid & 31;
    int w    = tid >> 5;
    if (tid == 0) carry = 0;
    __syncthreads();
    for (int base = 0; base < NNODE; base += 1024) {
        int i = base + tid;
        int v = (i < NNODE) ? deg[i] : 0;
        int s = v;
#pragma unroll
        for (int o = 1; o < 32; o <<= 1) {
            int t = __shfl_up_sync(0xffffffffu, s, o);
            if (lane >= o) s += t;
        }
        if (lane == 31) wsum[w] = s;
        __syncthreads();
        if (w == 0) {
            int ws = (lane < 32) ? wsum[lane] : 0;
#pragma unroll
            for (int o = 1; o < 32; o <<= 1) {
                int t = __shfl_up_sync(0xffffffffu, ws, o);
                if (lane >= o) ws += t;
            }
            wsum[lane] = ws;
        }
        __syncthreads();
        int wpre = (w == 0) ? 0 : wsum[w - 1];
        if (i < NNODE) {
            int e = carry + wpre + s - v;   // exclusive
            off[i] = e;
            cur[i] = e;
        }
        __syncthreads();
        if (tid == 0) carry += wsum[31];
        __syncthreads();
    }
    if (threadIdx.x == 0) off[NNODE] = carry;
}

__global__ void fill_k(const int* __restrict__ src, const int* __restrict__ dst,
                       int* __restrict__ cur, int* __restrict__ eidx) {
    int e = blockIdx.x * blockDim.x + threadIdx.x;
    if (e >= NEDGE) return;
    int p = atomicAdd(&cur[dst[e]], 1);
    eidx[p] = src[e];
}

// ---------------- CSR gather aggregation ----------------
// out[i] = (1+eps)*feat[i] + sum_{j in in(i)} feat[j]
template <int F4SHIFT>
__global__ void agg_k(const float4* __restrict__ feat, const float* __restrict__ eps,
                      const int* __restrict__ off, const int* __restrict__ eidx,
                      float4* __restrict__ out) {
    const int lanes = 1 << F4SHIFT;
    int node = blockIdx.x * (256 >> F4SHIFT) + (threadIdx.x >> F4SHIFT);
    int f    = threadIdx.x & (lanes - 1);
    if (node >= NNODE) return;
    float s = 1.0f + *eps;
    float4 x = feat[((size_t)node << F4SHIFT) + f];
    float4 a0 = make_float4(x.x * s, x.y * s, x.z * s, x.w * s);
    float4 a1 = make_float4(0.f, 0.f, 0.f, 0.f);
    float4 a2 = make_float4(0.f, 0.f, 0.f, 0.f);
    float4 a3 = make_float4(0.f, 0.f, 0.f, 0.f);
    int b = off[node], e = off[node + 1];
    int j = b;
    for (; j + 3 < e; j += 4) {
        int s0 = eidx[j], s1 = eidx[j + 1], s2 = eidx[j + 2], s3 = eidx[j + 3];
        float4 v0 = feat[((size_t)s0 << F4SHIFT) + f];
        float4 v1 = feat[((size_t)s1 << F4SHIFT) + f];
        float4 v2 = feat[((size_t)s2 << F4SHIFT) + f];
        float4 v3 = feat[((size_t)s3 << F4SHIFT) + f];
        a0.x += v0.x; a0.y += v0.y; a0.z += v0.z; a0.w += v0.w;
        a1.x += v1.x; a1.y += v1.y; a1.z += v1.z; a1.w += v1.w;
        a2.x += v2.x; a2.y += v2.y; a2.z += v2.z; a2.w += v2.w;
        a3.x += v3.x; a3.y += v3.y; a3.z += v3.z; a3.w += v3.w;
    }
    for (; j < e; j++) {
        float4 v = feat[((size_t)eidx[j] << F4SHIFT) + f];
        a0.x += v.x; a0.y += v.y; a0.z += v.z; a0.w += v.w;
    }
    a0.x += a1.x + a2.x + a3.x;
    a0.y += a1.y + a2.y + a3.y;
    a0.z += a1.z + a2.z + a3.z;
    a0.w += a1.w + a2.w + a3.w;
    out[((size_t)node << F4SHIFT) + f] = a0;
}

__global__ void count_k(const int* __restrict__ batch, float* __restrict__ cnt) {
    int i = blockIdx.x * blockDim.x + threadIdx.x;
    if (i < NNODE) atomicAdd(&cnt[batch[i]], 1.0f);
}

// ---------------- Pipelined TF32 tensor-core GEMM ----------------
// 2-stage pipeline -> 70.6 KB smem -> 3 CTAs/SM (24 warps, occ 37.5%).
#define LDA 36
#define LDB 132
#define ASZ (128 * LDA)
#define BSZ (32 * LDB)
#define STGSZ (ASZ + BSZ)
#define NSTAGE 2
#define GEMM_SMEM (NSTAGE * STGSZ * 4)   // 70656 bytes

__device__ __forceinline__ void gemm_load_slab(
    const float* __restrict__ A, const float* __restrict__ B,
    float* sm, int slot, int k0, int tid, int m0, int n0, int M, int K) {
    float* smA = sm + slot * STGSZ;
    float* smB = smA + ASZ;
#pragma unroll
    for (int t = 0; t < 4; t++) {
        int j   = tid + t * 256;
        int row = j >> 3;
        int c4  = (j & 7) * 4;
        bool ok = (m0 + row < M);
        const float* gs = &A[ok ? ((size_t)(m0 + row) * K + k0 + c4) : 0];
        cp_async16z(&smA[row * LDA + c4], gs, ok ? 16 : 0);
    }
#pragma unroll
    for (int t = 0; t < 4; t++) {
        int j   = tid + t * 256;
        int row = j >> 5;
        int c4  = (j & 31) * 4;
        cp_async16(&smB[row * LDB + c4], &B[(size_t)(k0 + row) * 256 + n0 + c4]);
    }
}

template <bool RELU, bool POOL>
__global__ __launch_bounds__(256)
void gemm_tc(const float* __restrict__ A, const float* __restrict__ B,
             const float* __restrict__ bias, float* __restrict__ C,
             const int* __restrict__ batch, float* __restrict__ psum,
             int M, int K) {
    extern __shared__ float sm[];

    int tid  = threadIdx.x;
    int wid  = tid >> 5;
    int lane = tid & 31;
    int wm = wid >> 1;
    int wn = wid & 1;
    int m0 = blockIdx.y * 128;
    int n0 = blockIdx.x * 128;

    wmma::fragment<wmma::accumulator, 16, 16, 8, float> acc[2][4];
#pragma unroll
    for (int i = 0; i < 2; i++)
#pragma unroll
        for (int j = 0; j < 4; j++) wmma::fill_fragment(acc[i][j], 0.0f);

    int iters = K >> 5;

#pragma unroll
    for (int i = 0; i < NSTAGE - 1; i++) {
        if (i < iters)
            gemm_load_slab(A, B, sm, i, i * 32, tid, m0, n0, M, K);
        cp_commit();
    }

    for (int it = 0; it < iters; it++) {
        int pf = it + NSTAGE - 1;
        if (pf < iters)
            gemm_load_slab(A, B, sm, pf % NSTAGE, pf * 32, tid, m0, n0, M, K);
        cp_commit();
        cp_wait<NSTAGE - 1>();
        __syncthreads();

        float* smA = sm + (it % NSTAGE) * STGSZ;
        float* smB = smA + ASZ;
#pragma unroll
        for (int ks = 0; ks < 4; ks++) {
            wmma::fragment<wmma::matrix_a, 16, 16, 8, wmma::precision::tf32,
                           wmma::row_major> af[2];
            wmma::fragment<wmma::matrix_b, 16, 16, 8, wmma::precision::tf32,
                           wmma::row_major> bf[4];
#pragma unroll
            for (int i = 0; i < 2; i++) {
                wmma::load_matrix_sync(af[i], &smA[(wm * 32 + i * 16) * LDA + ks * 8], LDA);
#pragma unroll
                for (int t = 0; t < af[i].num_elements; t++)
                    af[i].x[t] = wmma::__float_to_tf32(af[i].x[t]);
            }
#pragma unroll
            for (int j = 0; j < 4; j++)
                wmma::load_matrix_sync(bf[j], &smB[(ks * 8) * LDB + wn * 64 + j * 16], LDB);
#pragma unroll
            for (int i = 0; i < 2; i++)
#pragma unroll
                for (int j = 0; j < 4; j++)
                    wmma::mma_sync(acc[i][j], af[i], bf[j], acc[i][j]);
        }
        __syncthreads();
    }

    // ---- epilogue ----
    const int LDS_ = 20;
    float* St = sm + wid * (16 * LDS_);
#pragma unroll
    for (int i = 0; i < 2; i++)
#pragma unroll
        for (int j = 0; j < 4; j++) {
            wmma::store_matrix_sync(St, acc[i][j], LDS_, wmma::mem_row_major);
            __syncwarp();
            int r   = lane >> 1;
            int c   = (lane & 1) * 8;
            int row = m0 + wm * 32 + i * 16 + r;
            int col = n0 + wn * 64 + j * 16 + c;
            if (row < M) {
                float v[8];
#pragma unroll
                for (int u = 0; u < 8; u++) {
                    v[u] = St[r * LDS_ + c + u] + bias[col + u];
                    if (RELU) v[u] = fmaxf(v[u], 0.0f);
                }
                if (POOL) {
                    int g = batch[row];
                    float4* pp = (float4*)&psum[(size_t)g * 256 + col];
                    atomicAdd(&pp[0], make_float4(v[0], v[1], v[2], v[3]));
                    atomicAdd(&pp[1], make_float4(v[4], v[5], v[6], v[7]));
                } else {
                    float4* cp = (float4*)&C[(size_t)row * 256 + col];
                    cp[0] = make_float4(v[0], v[1], v[2], v[3]);
                    cp[1] = make_float4(v[4], v[5], v[6], v[7]);
                }
            }
            __syncwarp();
        }
}

// ---------------- final: mean, linear [256->10], log_softmax ----------------
__global__ void final_k(const float* __restrict__ psum, const float* __restrict__ cnt,
                        const float* __restrict__ Wlin, const float* __restrict__ blin,
                        float* __restrict__ out) {
    int g = blockIdx.x;
    int lane = threadIdx.x;
    float inv = 1.0f / fmaxf(cnt[g], 1.0f);
    float acc[FOUT];
#pragma unroll
    for (int o = 0; o < FOUT; o++) acc[o] = 0.0f;
    for (int h = lane; h < FH; h += 32) {
        float p = psum[g * FH + h] * inv;
#pragma unroll
        for (int o = 0; o < FOUT; o++) acc[o] += p * Wlin[h * FOUT + o];
    }
#pragma unroll
    for (int off = 16; off > 0; off >>= 1)
#pragma unroll
        for (int o = 0; o < FOUT; o++)
            acc[o] += __shfl_down_sync(0xffffffffu, acc[o], off);
    if (lane == 0) {
        float z[FOUT];
        float m = -1e30f;
#pragma unroll
        for (int o = 0; o < FOUT; o++) { z[o] = acc[o] + blin[o]; m = fmaxf(m, z[o]); }
        float s = 0.0f;
#pragma unroll
        for (int o = 0; o < FOUT; o++) s += __expf(z[o] - m);
        float l = logf(s);
#pragma unroll
        for (int o = 0; o < FOUT; o++) out[g * FOUT + o] = z[o] - m - l;
    }
}

// ---------------- launcher ----------------
extern "C" void kernel_launch(void* const* d_in, const int* in_sizes, int n_in,
                              void* d_out, int out_size) {
    const float* x     = (const float*)d_in[0];
    const int*   ei    = (const int*)  d_in[1];
    const int*   batch = (const int*)  d_in[2];
    const float* eps1  = (const float*)d_in[3];
    const float* W1a   = (const float*)d_in[4];
    const float* b1a   = (const float*)d_in[5];
    const float* W1b   = (const float*)d_in[6];
    const float* b1b   = (const float*)d_in[7];
    const float* eps2  = (const float*)d_in[8];
    const float* W2a   = (const float*)d_in[9];
    const float* b2a   = (const float*)d_in[10];
    const float* W2b   = (const float*)d_in[11];
    const float* b2b   = (const float*)d_in[12];
    const float* Wlin  = (const float*)d_in[13];
    const float* blin  = (const float*)d_in[14];
    float* out = (float*)d_out;

    void *p_agg1, *p_t1, *p_h, *p_agg2, *p_t2, *p_psum, *p_cnt;
    void *p_deg, *p_off, *p_cur, *p_eidx;
    void *p_w1a, *p_w1b, *p_w2a, *p_w2b;
    cudaGetSymbolAddress(&p_agg1, g_agg1);
    cudaGetSymbolAddress(&p_t1,   g_t1);
    cudaGetSymbolAddress(&p_h,    g_h);
    cudaGetSymbolAddress(&p_agg2, g_agg2);
    cudaGetSymbolAddress(&p_t2,   g_t2);
    cudaGetSymbolAddress(&p_psum, g_psum);
    cudaGetSymbolAddress(&p_cnt,  g_cnt);
    cudaGetSymbolAddress(&p_deg,  g_deg);
    cudaGetSymbolAddress(&p_off,  g_off);
    cudaGetSymbolAddress(&p_cur,  g_cur);
    cudaGetSymbolAddress(&p_eidx, g_eidx);
    cudaGetSymbolAddress(&p_w1a, g_W1a_t);
    cudaGetSymbolAddress(&p_w1b, g_W1b_t);
    cudaGetSymbolAddress(&p_w2a, g_W2a_t);
    cudaGetSymbolAddress(&p_w2b, g_W2b_t);
    float4* agg1 = (float4*)p_agg1;
    float4* t1   = (float4*)p_t1;
    float4* h    = (float4*)p_h;
    float4* agg2 = (float4*)p_agg2;
    float4* t2   = (float4*)p_t2;
    float*  psum = (float*)p_psum;
    float*  cnt  = (float*)p_cnt;
    int* deg  = (int*)p_deg;
    int* off  = (int*)p_off;
    int* cur  = (int*)p_cur;
    int* eidx = (int*)p_eidx;
    float*  W1a_t = (float*)p_w1a;
    float*  W1b_t = (float*)p_w1b;
    float*  W2a_t = (float*)p_w2a;
    float*  W2b_t = (float*)p_w2b;

    cudaFuncSetAttribute(gemm_tc<true,  false>,
                         cudaFuncAttributeMaxDynamicSharedMemorySize, GEMM_SMEM);
    cudaFuncSetAttribute(gemm_tc<false, true>,
                         cudaFuncAttributeMaxDynamicSharedMemorySize, GEMM_SMEM);

    const int* src = ei;
    const int* dst = ei + NEDGE;
    const int T = 256;

    // ---- CSR build (incoming edges per node) ----
    zeroi_k<<<(NNODE + T - 1) / T, T>>>(deg, NNODE);
    hist_k<<<(NEDGE + T - 1) / T, T>>>(dst, deg);
    scan_k<<<1, 1024>>>(deg, off, cur);
    fill_k<<<(NEDGE + T - 1) / T, T>>>(src, dst, cur, eidx);

    // ---- weights to tf32 (single launch) ----
    {
        int total = FIN * FH + 3 * FH * FH;
        wconv_all_k<<<(total + T - 1) / T, T>>>(W1a, W1b, W2a, W2b,
                                                W1a_t, W1b_t, W2a_t, W2b_t);
    }

    // ---- layer 1 ----
    agg_k<5><<<(NNODE * 32 + T - 1) / T, T>>>((const float4*)x, eps1, off, eidx, agg1);

    dim3 gdim(2, (NNODE + 127) / 128);
    gemm_tc<true, false><<<gdim, 256, GEMM_SMEM>>>(
        (const float*)agg1, W1a_t, b1a, (float*)t1, nullptr, nullptr, NNODE, FIN);
    gemm_tc<true, false><<<gdim, 256, GEMM_SMEM>>>(
        (const float*)t1, W1b_t, b1b, (float*)h, nullptr, nullptr, NNODE, FH);

    // ---- layer 2 ----
    agg_k<6><<<(NNODE * 64 + T - 1) / T, T>>>(h, eps2, off, eidx, agg2);
    gemm_tc<true, false><<<gdim, 256, GEMM_SMEM>>>(
        (const float*)agg2, W2a_t, b2a, (float*)t2, nullptr, nullptr, NNODE, FH);

    // ---- pooling setup (single zero launch) ----
    zero_pool_k<<<(NG * FH + NG + T - 1) / T, T>>>(psum, cnt);
    count_k<<<(NNODE + T - 1) / T, T>>>(batch, cnt);

    // h2 = t2 @ W2b + b2b fused with global-mean-pool partial sums
    gemm_tc<false, true><<<gdim, 256, GEMM_SMEM>>>(
        (const float*)t2, W2b_t, b2b, nullptr, batch, psum, NNODE, FH);

    // mean + linear + log_softmax
    final_k<<<NG, 32>>>(psum, cnt, Wlin, blin, out);
}

// round 15
// speedup vs baseline: 2.1903x; 1.8842x over previous
#include <cuda_runtime.h>
#include <mma.h>
#include <cuda_fp16.h>
#include <cstdint>

using namespace nvcuda;

// Problem constants (fixed by the dataset)
#define NNODE 50000
#define NEDGE 800000
#define FIN   128
#define FH    256
#define FOUT  10
#define NG    512

// ---------------- scratch (device globals; no allocation) ----------------
// fp16 feature buffers stored as uint4 (8 halves) for 16B alignment
__device__ uint4  g_xh  [NNODE * FIN / 8];
__device__ uint4  g_agg1[NNODE * FIN / 8];
__device__ uint4  g_t1  [NNODE * FH  / 8];
__device__ uint4  g_h   [NNODE * FH  / 8];
__device__ uint4  g_agg2[NNODE * FH  / 8];
__device__ uint4  g_t2  [NNODE * FH  / 8];
__device__ float4 g_psum[NG * FH / 4];
__device__ float  g_cnt [NG];
// CSR for incoming edges
__device__ int    g_deg [NNODE];
__device__ int    g_off [NNODE + 1];
__device__ int    g_cur [NNODE];
__device__ int    g_eidx[NEDGE];
// fp16 weights
__device__ uint4  g_W1a_h[FIN * FH / 8];
__device__ uint4  g_W1b_h[FH * FH / 8];
__device__ uint4  g_W2a_h[FH * FH / 8];
__device__ uint4  g_W2b_h[FH * FH / 8];

// ---------------- helpers ----------------
__device__ __forceinline__ void cp_async16(void* dst, const void* src) {
    uint32_t s = (uint32_t)__cvta_generic_to_shared(dst);
    asm volatile("cp.async.cg.shared.global [%0], [%1], 16;\n" :: "r"(s), "l"(src));
}
__device__ __forceinline__ void cp_async16z(void* dst, const void* src, int szbytes) {
    uint32_t s = (uint32_t)__cvta_generic_to_shared(dst);
    asm volatile("cp.async.cg.shared.global [%0], [%1], 16, %2;\n"
                 :: "r"(s), "l"(src), "r"(szbytes));
}
__device__ __forceinline__ void cp_commit() { asm volatile("cp.async.commit_group;\n"); }
template <int N>
__device__ __forceinline__ void cp_wait() { asm volatile("cp.async.wait_group %0;\n" :: "n"(N)); }

__device__ __forceinline__ unsigned h2u(__half2 v) {
    return *reinterpret_cast<unsigned*>(&v);
}
// unpack uint4 (8 fp16) -> 8 floats
__device__ __forceinline__ void cvt8(uint4 v, float* a) {
    __half2* p = reinterpret_cast<__half2*>(&v);
    float2 f0 = __half22float2(p[0]);
    float2 f1 = __half22float2(p[1]);
    float2 f2 = __half22float2(p[2]);
    float2 f3 = __half22float2(p[3]);
    a[0]=f0.x; a[1]=f0.y; a[2]=f1.x; a[3]=f1.y;
    a[4]=f2.x; a[5]=f2.y; a[6]=f3.x; a[7]=f3.y;
}
__device__ __forceinline__ void add8(uint4 v, float* a) {
    __half2* p = reinterpret_cast<__half2*>(&v);
    float2 f0 = __half22float2(p[0]);
    float2 f1 = __half22float2(p[1]);
    float2 f2 = __half22float2(p[2]);
    float2 f3 = __half22float2(p[3]);
    a[0]+=f0.x; a[1]+=f0.y; a[2]+=f1.x; a[3]+=f1.y;
    a[4]+=f2.x; a[5]+=f2.y; a[6]+=f3.x; a[7]+=f3.y;
}
__device__ __forceinline__ uint4 pack8(const float* a) {
    __half2 p0 = __floats2half2_rn(a[0], a[1]);
    __half2 p1 = __floats2half2_rn(a[2], a[3]);
    __half2 p2 = __floats2half2_rn(a[4], a[5]);
    __half2 p3 = __floats2half2_rn(a[6], a[7]);
    return make_uint4(h2u(p0), h2u(p1), h2u(p2), h2u(p3));
}

// ---------------- small utility kernels ----------------
__global__ void zero_pool_k(float* __restrict__ psum, float* __restrict__ cnt) {
    int i = blockIdx.x * blockDim.x + threadIdx.x;
    if (i < NG * FH) psum[i] = 0.0f;
    else if (i < NG * FH + NG) cnt[i - NG * FH] = 0.0f;
}
__global__ void zeroi_k(int* __restrict__ p, int n) {
    int i = blockIdx.x * blockDim.x + threadIdx.x;
    if (i < n) p[i] = 0;
}
// convert x + all four weight matrices fp32 -> fp16, one launch, float4-vectorized
__global__ void conv_all_k(const float4* __restrict__ x,
                           const float4* __restrict__ W1a, const float4* __restrict__ W1b,
                           const float4* __restrict__ W2a, const float4* __restrict__ W2b,
                           uint2* __restrict__ xh,
                           uint2* __restrict__ d1a, uint2* __restrict__ d1b,
                           uint2* __restrict__ d2a, uint2* __restrict__ d2b) {
    int i = blockIdx.x * blockDim.x + threadIdx.x;
    const int X4 = NNODE * FIN / 4;      // 1,600,000
    const int S1 = X4 + FIN * FH / 4;
    const int S2 = S1 + FH * FH / 4;
    const int S3 = S2 + FH * FH / 4;
    const int S4 = S3 + FH * FH / 4;
    float4 v; uint2* o; int k;
    if (i < X4)      { v = x[i];        o = xh;  k = i; }
    else if (i < S1) { v = W1a[i - X4]; o = d1a; k = i - X4; }
    else if (i < S2) { v = W1b[i - S1]; o = d1b; k = i - S1; }
    else if (i < S3) { v = W2a[i - S2]; o = d2a; k = i - S2; }
    else if (i < S4) { v = W2b[i - S3]; o = d2b; k = i - S3; }
    else return;
    __half2 lo = __floats2half2_rn(v.x, v.y);
    __half2 hi = __floats2half2_rn(v.z, v.w);
    o[k] = make_uint2(h2u(lo), h2u(hi));
}

// ---------------- CSR build ----------------
__global__ void hist_k(const int* __restrict__ dst, int* __restrict__ deg) {
    int e = blockIdx.x * blockDim.x + threadIdx.x;
    if (e < NEDGE) atomicAdd(&deg[dst[e]], 1);
}

__global__ void scan_k(const int* __restrict__ deg, int* __restrict__ off,
                       int* __restrict__ cur) {
    __shared__ int wsum[32];
    __shared__ int carry;
    int tid  = threadIdx.x;
    int lane = tid & 31;
    int w    = tid >> 5;
    if (tid == 0) carry = 0;
    __syncthreads();
    for (int base = 0; base < NNODE; base += 1024) {
        int i = base + tid;
        int v = (i < NNODE) ? deg[i] : 0;
        int s = v;
#pragma unroll
        for (int o = 1; o < 32; o <<= 1) {
            int t = __shfl_up_sync(0xffffffffu, s, o);
            if (lane >= o) s += t;
        }
        if (lane == 31) wsum[w] = s;
        __syncthreads();
        if (w == 0) {
            int ws = (lane < 32) ? wsum[lane] : 0;
#pragma unroll
            for (int o = 1; o < 32; o <<= 1) {
                int t = __shfl_up_sync(0xffffffffu, ws, o);
                if (lane >= o) ws += t;
            }
            wsum[lane] = ws;
        }
        __syncthreads();
        int wpre = (w == 0) ? 0 : wsum[w - 1];
        if (i < NNODE) {
            int e = carry + wpre + s - v;
            off[i] = e;
            cur[i] = e;
        }
        __syncthreads();
        if (tid == 0) carry += wsum[31];
        __syncthreads();
    }
    if (threadIdx.x == 0) off[NNODE] = carry;
}

__global__ void fill_k(const int* __restrict__ src, const int* __restrict__ dst,
                       int* __restrict__ cur, int* __restrict__ eidx) {
    int e = blockIdx.x * blockDim.x + threadIdx.x;
    if (e >= NEDGE) return;
    int p = atomicAdd(&cur[dst[e]], 1);
    eidx[p] = src[e];
}

// ---------------- CSR gather aggregation over fp16 features ----------------
// out[i] = fp16( (1+eps)*feat[i] + sum_{j in in(i)} feat[j] ),  fp32 accumulation
// LSHIFT: log2(uint4 lanes per node): FIN -> 4 (16 lanes), FH -> 5 (32 lanes)
template <int LSHIFT>
__global__ void aggh_k(const uint4* __restrict__ feat, const float* __restrict__ eps,
                       const int* __restrict__ off, const int* __restrict__ eidx,
                       uint4* __restrict__ out) {
    const int lanes = 1 << LSHIFT;
    int node = blockIdx.x * (256 >> LSHIFT) + (threadIdx.x >> LSHIFT);
    int f    = threadIdx.x & (lanes - 1);
    if (node >= NNODE) return;
    float s = 1.0f + *eps;
    float a0[8], a1[8], a2[8], a3[8];
    cvt8(feat[((size_t)node << LSHIFT) + f], a0);
#pragma unroll
    for (int k = 0; k < 8; k++) { a0[k] *= s; a1[k] = 0.f; a2[k] = 0.f; a3[k] = 0.f; }
    int b = off[node], e = off[node + 1];
    int j = b;
    for (; j + 3 < e; j += 4) {
        int s0 = eidx[j], s1 = eidx[j + 1], s2 = eidx[j + 2], s3 = eidx[j + 3];
        add8(feat[((size_t)s0 << LSHIFT) + f], a0);
        add8(feat[((size_t)s1 << LSHIFT) + f], a1);
        add8(feat[((size_t)s2 << LSHIFT) + f], a2);
        add8(feat[((size_t)s3 << LSHIFT) + f], a3);
    }
    for (; j < e; j++)
        add8(feat[((size_t)eidx[j] << LSHIFT) + f], a0);
#pragma unroll
    for (int k = 0; k < 8; k++) a0[k] += a1[k] + a2[k] + a3[k];
    out[((size_t)node << LSHIFT) + f] = pack8(a0);
}

__global__ void count_k(const int* __restrict__ batch, float* __restrict__ cnt) {
    int i = blockIdx.x * blockDim.x + threadIdx.x;
    if (i < NNODE) atomicAdd(&cnt[batch[i]], 1.0f);
}

// ---------------- Pipelined FP16 tensor-core GEMM ----------------
// C[M,256] = A[M,K] @ B[K,256] + bias, fp32 accumulate, fp16 in/out.
// 128x128 CTA tile, BK=32, 2-stage cp.async, 8 warps (4x2), warp 32x64.
#define LDA_H 40
#define LDB_H 136
#define ASZ_H (128 * LDA_H)        // 5120 halves
#define BSZ_H (32 * LDB_H)         // 4352 halves
#define STG_H (ASZ_H + BSZ_H)      // 9472 halves
#define NSTAGE 2
#define GEMM_SMEM (NSTAGE * STG_H * 2)   // 37888 bytes

__device__ __forceinline__ void gemm_load_slab(
    const __half* __restrict__ A, const __half* __restrict__ B,
    __half* smh, int slot, int k0, int tid, int m0, int n0, int M, int K) {
    __half* smA = smh + slot * STG_H;
    __half* smB = smA + ASZ_H;
#pragma unroll
    for (int t = 0; t < 2; t++) {
        int j   = tid + t * 256;       // 0..511 chunks of 8 halves
        int row = j >> 2;              // 0..127
        int c8  = (j & 3) * 8;         // 0..24
        bool ok = (m0 + row < M);
        const __half* gs = &A[ok ? ((size_t)(m0 + row) * K + k0 + c8) : 0];
        cp_async16z(&smA[row * LDA_H + c8], gs, ok ? 16 : 0);
    }
#pragma unroll
    for (int t = 0; t < 2; t++) {
        int j   = tid + t * 256;
        int row = j >> 4;              // 0..31
        int c8  = (j & 15) * 8;        // 0..120
        cp_async16(&smB[row * LDB_H + c8], &B[(size_t)(k0 + row) * 256 + n0 + c8]);
    }
}

template <bool RELU, bool POOL>
__global__ __launch_bounds__(256)
void gemm_tc(const __half* __restrict__ A, const __half* __restrict__ B,
             const float* __restrict__ bias, __half* __restrict__ C,
             const int* __restrict__ batch, float* __restrict__ psum,
             int M, int K) {
    extern __shared__ __half smh[];

    int tid  = threadIdx.x;
    int wid  = tid >> 5;
    int lane = tid & 31;
    int wm = wid >> 1;
    int wn = wid & 1;
    int m0 = blockIdx.y * 128;
    int n0 = blockIdx.x * 128;

    wmma::fragment<wmma::accumulator, 16, 16, 16, float> acc[2][4];
#pragma unroll
    for (int i = 0; i < 2; i++)
#pragma unroll
        for (int j = 0; j < 4; j++) wmma::fill_fragment(acc[i][j], 0.0f);

    int iters = K >> 5;

    // prologue
    gemm_load_slab(A, B, smh, 0, 0, tid, m0, n0, M, K);
    cp_commit();

    for (int it = 0; it < iters; it++) {
        int pf = it + 1;
        if (pf < iters)
            gemm_load_slab(A, B, smh, pf & 1, pf * 32, tid, m0, n0, M, K);
        cp_commit();
        cp_wait<1>();
        __syncthreads();

        __half* smA = smh + (it & 1) * STG_H;
        __half* smB = smA + ASZ_H;
#pragma unroll
        for (int ks = 0; ks < 2; ks++) {
            wmma::fragment<wmma::matrix_a, 16, 16, 16, half,
                           wmma::row_major> af[2];
            wmma::fragment<wmma::matrix_b, 16, 16, 16, half,
                           wmma::row_major> bf[4];
#pragma unroll
            for (int i = 0; i < 2; i++)
                wmma::load_matrix_sync(af[i], &smA[(wm * 32 + i * 16) * LDA_H + ks * 16], LDA_H);
#pragma unroll
            for (int j = 0; j < 4; j++)
                wmma::load_matrix_sync(bf[j], &smB[(ks * 16) * LDB_H + wn * 64 + j * 16], LDB_H);
#pragma unroll
            for (int i = 0; i < 2; i++)
#pragma unroll
                for (int j = 0; j < 4; j++)
                    wmma::mma_sync(acc[i][j], af[i], bf[j], acc[i][j]);
        }
        __syncthreads();
    }

    // ---- epilogue via per-warp fp32 smem staging (reuse tile smem) ----
    const int LDS_ = 20;
    float* St = reinterpret_cast<float*>(smh) + wid * (16 * LDS_);
#pragma unroll
    for (int i = 0; i < 2; i++)
#pragma unroll
        for (int j = 0; j < 4; j++) {
            wmma::store_matrix_sync(St, acc[i][j], LDS_, wmma::mem_row_major);
            __syncwarp();
            int r   = lane >> 1;
            int c   = (lane & 1) * 8;
            int row = m0 + wm * 32 + i * 16 + r;
            int col = n0 + wn * 64 + j * 16 + c;
            if (row < M) {
                float v[8];
#pragma unroll
                for (int u = 0; u < 8; u++) {
                    v[u] = St[r * LDS_ + c + u] + bias[col + u];
                    if (RELU) v[u] = fmaxf(v[u], 0.0f);
                }
                if (POOL) {
                    int g = batch[row];
                    float4* pp = (float4*)&psum[(size_t)g * 256 + col];
                    atomicAdd(&pp[0], make_float4(v[0], v[1], v[2], v[3]));
                    atomicAdd(&pp[1], make_float4(v[4], v[5], v[6], v[7]));
                } else {
                    *reinterpret_cast<uint4*>(&C[(size_t)row * 256 + col]) = pack8(v);
                }
            }
            __syncwarp();
        }
}

// ---------------- final: mean, linear [256->10], log_softmax ----------------
__global__ void final_k(const float* __restrict__ psum, const float* __restrict__ cnt,
                        const float* __restrict__ Wlin, const float* __restrict__ blin,
                        float* __restrict__ out) {
    int g = blockIdx.x;
    int lane = threadIdx.x;
    float inv = 1.0f / fmaxf(cnt[g], 1.0f);
    float acc[FOUT];
#pragma unroll
    for (int o = 0; o < FOUT; o++) acc[o] = 0.0f;
    for (int h = lane; h < FH; h += 32) {
        float p = psum[g * FH + h] * inv;
#pragma unroll
        for (int o = 0; o < FOUT; o++) acc[o] += p * Wlin[h * FOUT + o];
    }
#pragma unroll
    for (int off = 16; off > 0; off >>= 1)
#pragma unroll
        for (int o = 0; o < FOUT; o++)
            acc[o] += __shfl_down_sync(0xffffffffu, acc[o], off);
    if (lane == 0) {
        float z[FOUT];
        float m = -1e30f;
#pragma unroll
        for (int o = 0; o < FOUT; o++) { z[o] = acc[o] + blin[o]; m = fmaxf(m, z[o]); }
        float s = 0.0f;
#pragma unroll
        for (int o = 0; o < FOUT; o++) s += __expf(z[o] - m);
        float l = logf(s);
#pragma unroll
        for (int o = 0; o < FOUT; o++) out[g * FOUT + o] = z[o] - m - l;
    }
}

// ---------------- launcher ----------------
extern "C" void kernel_launch(void* const* d_in, const int* in_sizes, int n_in,
                              void* d_out, int out_size) {
    const float* x     = (const float*)d_in[0];
    const int*   ei    = (const int*)  d_in[1];
    const int*   batch = (const int*)  d_in[2];
    const float* eps1  = (const float*)d_in[3];
    const float* W1a   = (const float*)d_in[4];
    const float* b1a   = (const float*)d_in[5];
    const float* W1b   = (const float*)d_in[6];
    const float* b1b   = (const float*)d_in[7];
    const float* eps2  = (const float*)d_in[8];
    const float* W2a   = (const float*)d_in[9];
    const float* b2a   = (const float*)d_in[10];
    const float* W2b   = (const float*)d_in[11];
    const float* b2b   = (const float*)d_in[12];
    const float* Wlin  = (const float*)d_in[13];
    const float* blin  = (const float*)d_in[14];
    float* out = (float*)d_out;

    void *p_xh, *p_agg1, *p_t1, *p_h, *p_agg2, *p_t2, *p_psum, *p_cnt;
    void *p_deg, *p_off, *p_cur, *p_eidx;
    void *p_w1a, *p_w1b, *p_w2a, *p_w2b;
    cudaGetSymbolAddress(&p_xh,   g_xh);
    cudaGetSymbolAddress(&p_agg1, g_agg1);
    cudaGetSymbolAddress(&p_t1,   g_t1);
    cudaGetSymbolAddress(&p_h,    g_h);
    cudaGetSymbolAddress(&p_agg2, g_agg2);
    cudaGetSymbolAddress(&p_t2,   g_t2);
    cudaGetSymbolAddress(&p_psum, g_psum);
    cudaGetSymbolAddress(&p_cnt,  g_cnt);
    cudaGetSymbolAddress(&p_deg,  g_deg);
    cudaGetSymbolAddress(&p_off,  g_off);
    cudaGetSymbolAddress(&p_cur,  g_cur);
    cudaGetSymbolAddress(&p_eidx, g_eidx);
    cudaGetSymbolAddress(&p_w1a, g_W1a_h);
    cudaGetSymbolAddress(&p_w1b, g_W1b_h);
    cudaGetSymbolAddress(&p_w2a, g_W2a_h);
    cudaGetSymbolAddress(&p_w2b, g_W2b_h);
    uint4* xh   = (uint4*)p_xh;
    uint4* agg1 = (uint4*)p_agg1;
    uint4* t1   = (uint4*)p_t1;
    uint4* h    = (uint4*)p_h;
    uint4* agg2 = (uint4*)p_agg2;
    uint4* t2   = (uint4*)p_t2;
    float* psum = (float*)p_psum;
    float* cnt  = (float*)p_cnt;
    int* deg  = (int*)p_deg;
    int* off  = (int*)p_off;
    int* cur  = (int*)p_cur;
    int* eidx = (int*)p_eidx;
    __half* W1a_h = (__half*)p_w1a;
    __half* W1b_h = (__half*)p_w1b;
    __half* W2a_h = (__half*)p_w2a;
    __half* W2b_h = (__half*)p_w2b;

    cudaFuncSetAttribute(gemm_tc<true,  false>,
                         cudaFuncAttributeMaxDynamicSharedMemorySize, GEMM_SMEM);
    cudaFuncSetAttribute(gemm_tc<false, true>,
                         cudaFuncAttributeMaxDynamicSharedMemorySize, GEMM_SMEM);

    const int* src = ei;
    const int* dst = ei + NEDGE;
    const int T = 256;

    // ---- CSR build ----
    zeroi_k<<<(NNODE + T - 1) / T, T>>>(deg, NNODE);
    hist_k<<<(NEDGE + T - 1) / T, T>>>(dst, deg);
    scan_k<<<1, 1024>>>(deg, off, cur);
    fill_k<<<(NEDGE + T - 1) / T, T>>>(src, dst, cur, eidx);

    // ---- x + weights to fp16 (single launch) ----
    {
        int total4 = NNODE * FIN / 4 + (FIN * FH + 3 * FH * FH) / 4;
        conv_all_k<<<(total4 + T - 1) / T, T>>>(
            (const float4*)x, (const float4*)W1a, (const float4*)W1b,
            (const float4*)W2a, (const float4*)W2b,
            (uint2*)xh, (uint2*)W1a_h, (uint2*)W1b_h, (uint2*)W2a_h, (uint2*)W2b_h);
    }

    // ---- layer 1 ----
    aggh_k<4><<<(NNODE + 15) / 16, T>>>(xh, eps1, off, eidx, agg1);

    dim3 gdim(2, (NNODE + 127) / 128);
    gemm_tc<true, false><<<gdim, 256, GEMM_SMEM>>>(
        (const __half*)agg1, W1a_h, b1a, (__half*)t1,
        nullptr, nullptr, NNODE, FIN);
    gemm_tc<true, false><<<gdim, 256, GEMM_SMEM>>>(
        (const __half*)t1, W1b_h, b1b, (__half*)h,
        nullptr, nullptr, NNODE, FH);

    // ---- layer 2 ----
    aggh_k<5><<<(NNODE + 7) / 8, T>>>(h, eps2, off, eidx, agg2);
    gemm_tc<true, false><<<gdim, 256, GEMM_SMEM>>>(
        (const __half*)agg2, W2a_h, b2a, (__half*)t2,
        nullptr, nullptr, NNODE, FH);

    // ---- pooling setup ----
    zero_pool_k<<<(NG * FH + NG + T - 1) / T, T>>>(psum, cnt);
    count_k<<<(NNODE + T - 1) / T, T>>>(batch, cnt);

    // h2 GEMM fused with global-mean-pool partial sums
    gemm_tc<false, true><<<gdim, 256, GEMM_SMEM>>>(
        (const __half*)t2, W2b_h, b2b, nullptr,
        batch, psum, NNODE, FH);

    // mean + linear + log_softmax
    final_k<<<NG, 32>>>(psum, cnt, Wlin, blin, out);
}